// round 16
// baseline (speedup 1.0000x reference)
#include <cuda_runtime.h>
#include <cuda_fp16.h>
#include <cstdint>

#define BATCH 4096
#define NF 16
#define FS 64
#define EMBD 64
#define NPAIRS 120
#define K0 15424
#define N0 1024
#define N1 512
#define N2 256
#define BN_EPS 1e-5f

// ---------------- scratch ----------------
__device__ __align__(16) __half g_sparseh[BATCH * NF * FS];
__device__ __align__(16) __half g_embWh[NF * EMBD * FS];
__device__ __align__(16) __half g_embh[BATCH * NF * EMBD];
__device__ __align__(16) float  g_z[BATCH * NF];
__device__ __align__(16) __half g_dnn[(size_t)BATCH * K0];
__device__ __align__(16) __half g_W0h[(size_t)N0 * K0];
__device__ __align__(16) __half g_W1h[N1 * N0];
__device__ __align__(16) __half g_W2h[N2 * N1];
__device__ __align__(16) __half g_biWh[NPAIRS * EMBD * EMBD];
__device__ __align__(16) __half g_h0h[BATCH * N0];
__device__ __align__(16) __half g_h1h[BATCH * N1];
__device__ __align__(16) __half g_h2h[BATCH * N2];
__device__ __align__(16) float  g_cs[1792];
__device__ __align__(16) float  g_cq[1792];
__device__ float g_v[BATCH];
__device__ float g_lin[BATCH];

__device__ __forceinline__ float sigmoidf(float x) {
    return 1.0f / (1.0f + __expf(-x));
}

__device__ __forceinline__ uint32_t smem_u32(const void* p) {
    uint32_t a;
    asm("{ .reg .u64 t; cvta.to.shared.u64 t, %1; cvt.u32.u64 %0, t; }" : "=r"(a) : "l"(p));
    return a;
}

__device__ __forceinline__ void mma_f16(float c[4], const uint32_t a[4], const uint32_t b[2]) {
    asm volatile(
        "mma.sync.aligned.m16n8k16.row.col.f32.f16.f16.f32 "
        "{%0,%1,%2,%3}, {%4,%5,%6,%7}, {%8,%9}, {%0,%1,%2,%3};"
        : "+f"(c[0]), "+f"(c[1]), "+f"(c[2]), "+f"(c[3])
        : "r"(a[0]), "r"(a[1]), "r"(a[2]), "r"(a[3]), "r"(b[0]), "r"(b[1]));
}

__device__ __forceinline__ void ldsm_x4(uint32_t r[4], uint32_t addr) {
    asm volatile("ldmatrix.sync.aligned.m8n8.x4.shared.b16 {%0,%1,%2,%3}, [%4];"
        : "=r"(r[0]), "=r"(r[1]), "=r"(r[2]), "=r"(r[3]) : "r"(addr));
}
__device__ __forceinline__ void ldsm_x2(uint32_t r[2], uint32_t addr) {
    asm volatile("ldmatrix.sync.aligned.m8n8.x2.shared.b16 {%0,%1}, [%2];"
        : "=r"(r[0]), "=r"(r[1]) : "r"(addr));
}
__device__ __forceinline__ void cp_async16(uint32_t dst, const void* src) {
    asm volatile("cp.async.cg.shared.global [%0], [%1], 16;" :: "r"(dst), "l"(src));
}
#define CP_COMMIT() asm volatile("cp.async.commit_group;" ::: "memory")
#define CP_WAIT(n)  asm volatile("cp.async.wait_group %0;" :: "n"(n) : "memory")

#define ROWB 144

// ================= launch 0: fused conversions + stats zeroing =============
#define CC_W0 3948544u
#define CC_SP 4997120u
#define CC_W1 5128192u
#define CC_W2 5160960u
#define CC_BI 5283840u
#define CC_EW 5300224u
#define CC_DE 5365760u
#define CC_TOT (CC_DE + 896u)

__global__ void conv_all_kernel(const float* __restrict__ W0, const float* __restrict__ sparse,
                                const float* __restrict__ W1, const float* __restrict__ W2,
                                const float* __restrict__ biW, const float* __restrict__ embW,
                                const float* __restrict__ dense) {
    uint32_t idx = blockIdx.x * 256 + threadIdx.x;
    if (idx >= CC_TOT) return;
    const float* src;
    __half* dst;
    size_t off;
    if (idx < CC_W0)      { src = W0;     dst = g_W0h;     off = idx; }
    else if (idx < CC_SP) { src = sparse; dst = g_sparseh; off = idx - CC_W0; }
    else if (idx < CC_W1) { src = W1;     dst = g_W1h;     off = idx - CC_SP; }
    else if (idx < CC_W2) { src = W2;     dst = g_W2h;     off = idx - CC_W1; }
    else if (idx < CC_BI) { src = biW;    dst = g_biWh;    off = idx - CC_W2; }
    else if (idx < CC_EW) { src = embW;   dst = g_embWh;   off = idx - CC_BI; }
    else if (idx < CC_DE) {
        uint32_t o = (idx - CC_EW) * 4;
        int b = o >> 6, d = o & 63;
        float4 v = *(const float4*)(dense + o);
        __half2* dd = (__half2*)&g_dnn[(size_t)b * K0 + 15360 + d];
        dd[0] = __floats2half2_rn(v.x, v.y);
        dd[1] = __floats2half2_rn(v.z, v.w);
        return;
    } else {
        uint32_t k = (idx - CC_DE) * 4;
        float4 z = {0.f, 0.f, 0.f, 0.f};
        if (k < 1792) *(float4*)&g_cs[k] = z;
        else *(float4*)&g_cq[k - 1792] = z;
        return;
    }
    float4 v = *(const float4*)(src + off * 4);
    __half2* d2 = (__half2*)(dst + off * 4);
    d2[0] = __floats2half2_rn(v.x, v.y);
    d2[1] = __floats2half2_rn(v.z, v.w);
}

// ================= launch 1: embed mma + row-sum partials ==================
#define EM_X 0
#define EM_W 18432
#define EM_SMEM 27648

__global__ void __launch_bounds__(256)
embed_mma_kernel() {
    __shared__ __align__(128) char sm[EM_SMEM];
    __shared__ float zp[128][8];
    uint32_t sb = smem_u32(sm);
    int t = threadIdx.x;
    int lane = t & 31, warp = t >> 5;
    int wm = warp >> 1;
    int wn = warp & 1;
    int gg = blockIdx.y;
    int b0 = blockIdx.x * 128;

#pragma unroll
    for (int c0 = 0; c0 < 1536; c0 += 256) {
        int c = c0 + t;
        if (c < 1024) {
            int r = c >> 3, ch = c & 7;
            cp_async16(sb + EM_X + r * ROWB + ch * 16,
                       g_sparseh + (size_t)(b0 + r) * 1024 + gg * 64 + ch * 8);
        } else {
            int r = (c - 1024) >> 3, ch = c & 7;
            cp_async16(sb + EM_W + r * ROWB + ch * 16,
                       g_embWh + gg * 4096 + r * 64 + ch * 8);
        }
    }
    CP_COMMIT();
    CP_WAIT(0);
    __syncthreads();

    int q = lane >> 3, r8 = lane & 7;
    uint32_t a_off = sb + EM_X + (uint32_t)((wm * 32 + (q & 1) * 8 + r8) * ROWB + (q >> 1) * 16);
    uint32_t b_off = sb + EM_W + (uint32_t)((wn * 32 + r8) * ROWB + (q & 1) * 16);

    float acc[2][4][4] = {};
#pragma unroll
    for (int ks = 0; ks < 4; ks++) {
        uint32_t kb = ks * 32;
        uint32_t aF[2][4], bF[4][2];
#pragma unroll
        for (int mt = 0; mt < 2; mt++)
            ldsm_x4(aF[mt], a_off + mt * 16 * ROWB + kb);
#pragma unroll
        for (int nt = 0; nt < 4; nt++)
            ldsm_x2(bF[nt], b_off + nt * 8 * ROWB + kb);
#pragma unroll
        for (int mt = 0; mt < 2; mt++)
#pragma unroll
            for (int nt = 0; nt < 4; nt++)
                mma_f16(acc[mt][nt], aF[mt], bF[nt]);
    }

    int g = lane >> 2, tig = lane & 3;
#pragma unroll
    for (int mt = 0; mt < 2; mt++) {
#pragma unroll
        for (int h = 0; h < 2; h++) {
            int row = wm * 32 + mt * 16 + g + h * 8;
            float part = 0.f;
#pragma unroll
            for (int nt = 0; nt < 4; nt++) {
                int col = wn * 32 + nt * 8 + 2 * tig;
                float a0 = acc[mt][nt][h * 2 + 0], a1 = acc[mt][nt][h * 2 + 1];
                size_t base = (size_t)(b0 + row) * 1024 + gg * 64 + col;
                *(__half2*)&g_embh[base] = __floats2half2_rn(a0, a1);
                part += a0 + a1;
            }
            zp[row][wn * 4 + tig] = part;
        }
    }
    __syncthreads();
    if (t < 128) {
        float s = 0.f;
#pragma unroll
        for (int k = 0; k < 8; k++) s += zp[t][k];
        g_z[(b0 + t) * 16 + gg] = s;
    }
}

// ================= launch 2: bilinear mma + in-block senet MLP =============
#define BL_VI 0
#define BL_VJ 18432
#define BL_W  36864
#define BL_GA 46080
#define BL_SMEM 46592

__global__ void __launch_bounds__(256)
bilinear_mma_kernel(const __half* __restrict__ biWh,
                    const float* __restrict__ seW1, const float* __restrict__ seW2) {
    __shared__ __align__(128) char sm[BL_SMEM];
    uint32_t sb = smem_u32(sm);
    int t = threadIdx.x;
    int lane = t & 31, warp = t >> 5;
    int wm = warp >> 1;
    int wn = warp & 1;

    int p = blockIdx.y;
    int i = 0, rem = p, cnt = 15;
    while (rem >= cnt) { rem -= cnt; i++; cnt--; }
    int jf = i + 1 + rem;
    int b0 = blockIdx.x * 128;

#pragma unroll
    for (int c0 = 0; c0 < 2560; c0 += 256) {
        int c = c0 + t;
        if (c < 1024) {
            int r = c >> 3, ch = c & 7;
            cp_async16(sb + BL_VI + r * ROWB + ch * 16,
                       g_embh + (size_t)(b0 + r) * 1024 + i * 64 + ch * 8);
        } else if (c < 2048) {
            int r = (c - 1024) >> 3, ch = c & 7;
            cp_async16(sb + BL_VJ + r * ROWB + ch * 16,
                       g_embh + (size_t)(b0 + r) * 1024 + jf * 64 + ch * 8);
        } else {
            int r = (c - 2048) >> 3, ch = c & 7;
            cp_async16(sb + BL_W + r * ROWB + ch * 16,
                       biWh + (size_t)p * 4096 + r * 64 + ch * 8);
        }
    }
    if (t < 128) {
        int row = b0 + t;
        float zs[16];
#pragma unroll
        for (int k = 0; k < 16; k++) zs[k] = g_z[row * 16 + k] * (1.0f / 64.0f);
        float hv[4];
#pragma unroll
        for (int tt = 0; tt < 4; tt++) {
            float s = 0.f;
#pragma unroll
            for (int k = 0; k < 16; k++) s += zs[k] * seW1[tt * 16 + k];
            hv[tt] = fmaxf(s, 0.f);
        }
        float ai = 0.f, aj = 0.f;
#pragma unroll
        for (int tt = 0; tt < 4; tt++) {
            ai += hv[tt] * seW2[i * 4 + tt];
            aj += hv[tt] * seW2[jf * 4 + tt];
        }
        *(float*)(sm + BL_GA + t * 4) = fmaxf(ai, 0.f) * fmaxf(aj, 0.f);
    }
    CP_COMMIT();
    CP_WAIT(0);
    __syncthreads();

    int q = lane >> 3, r8 = lane & 7;
    uint32_t a_off = sb + BL_VI + (uint32_t)((wm * 32 + (q & 1) * 8 + r8) * ROWB + (q >> 1) * 16);
    uint32_t b_off = sb + BL_W + (uint32_t)((wn * 32 + r8) * ROWB + (q & 1) * 16);

    float acc[2][4][4] = {};
#pragma unroll
    for (int ks = 0; ks < 4; ks++) {
        uint32_t kb = ks * 32;
        uint32_t aF[2][4], bF[4][2];
#pragma unroll
        for (int mt = 0; mt < 2; mt++)
            ldsm_x4(aF[mt], a_off + mt * 16 * ROWB + kb);
#pragma unroll
        for (int nt = 0; nt < 4; nt++)
            ldsm_x2(bF[nt], b_off + nt * 8 * ROWB + kb);
#pragma unroll
        for (int mt = 0; mt < 2; mt++)
#pragma unroll
            for (int nt = 0; nt < 4; nt++)
                mma_f16(acc[mt][nt], aF[mt], bF[nt]);
    }
    __syncthreads();

    int g = lane >> 2, tig = lane & 3;
#pragma unroll
    for (int mt = 0; mt < 2; mt++) {
#pragma unroll
        for (int nt = 0; nt < 4; nt++) {
            int col = wn * 32 + nt * 8 + 2 * tig;
#pragma unroll
            for (int h = 0; h < 2; h++) {
                int row = wm * 32 + mt * 16 + g + h * 8;
                __half2 vj = *(__half2*)(sm + BL_VJ + row * ROWB + col * 2);
                float p0 = acc[mt][nt][h * 2 + 0] * __half2float(vj.x);
                float p1 = acc[mt][nt][h * 2 + 1] * __half2float(vj.y);
                *(__half2*)(sm + BL_VI + row * ROWB + col * 2) = __floats2half2_rn(p0, p1);
            }
        }
    }
    __syncthreads();

#pragma unroll
    for (int c0 = 0; c0 < 1024; c0 += 256) {
        int c = c0 + t;
        int row = c >> 3, ch = c & 7;
        uint4 v = *(uint4*)(sm + BL_VI + row * ROWB + ch * 16);
        size_t base = (size_t)(b0 + row) * K0 + p * 64 + ch * 8;
        *(uint4*)&g_dnn[base] = v;
        float s = *(float*)(sm + BL_GA + row * 4);
        __half2 s2 = __floats2half2_rn(s, s);
        __half2* hv = (__half2*)&v;
        hv[0] = __hmul2(hv[0], s2);
        hv[1] = __hmul2(hv[1], s2);
        hv[2] = __hmul2(hv[2], s2);
        hv[3] = __hmul2(hv[3], s2);
        *(uint4*)&g_dnn[base + 7680] = v;
    }
}

// ================= FP16 GEMM 128x128, 4 warps (2m x 2n, 64x64), GNS=3 ======
// 2 CTAs/SM. Loads hoisted above compute for ~2-iteration cp.async cover.
#define GTM 128
#define GTN 128
#define GBK 64
#define GNS 3
#define A_ST (GTM * ROWB)
#define B_ST (GTN * ROWB)
#define STB  (A_ST + B_ST)
#define GSMEM (GNS * STB)        // 110592

__global__ void __launch_bounds__(128, 2)
hgemm_kernel(const __half* __restrict__ A, const __half* __restrict__ Bw,
             __half* __restrict__ C, float* __restrict__ cs, float* __restrict__ cq,
             int N, int K) {
    extern __shared__ __align__(128) char smem[];
    uint32_t sb = smem_u32(smem);
    int t = threadIdx.x;
    int lane = t & 31, warp = t >> 5;
    int wm = warp & 1;
    int wn = warp >> 1;

    const __half* Ag = A + (size_t)(blockIdx.y * GTM) * K;
    const __half* Bg = Bw + (size_t)(blockIdx.x * GTN) * K;
    int nk = K / GBK;

    int q = lane >> 3, r8 = lane & 7;
    uint32_t a_off = (uint32_t)((wm * 64 + (q & 1) * 8 + r8) * ROWB + (q >> 1) * 16);
    uint32_t b_off = (uint32_t)(A_ST + (wn * 64 + (q >> 1) * 8 + r8) * ROWB + (q & 1) * 16);

    auto load_stage = [&](int slot, int kt) {
        uint32_t sdst = sb + slot * STB;
        int koff = kt * GBK;
#pragma unroll
        for (int c0 = 0; c0 < 2048; c0 += 128) {
            int c = c0 + t;
            if (c < 1024) {
                int r = c >> 3, ch = c & 7;
                cp_async16(sdst + r * ROWB + ch * 16, Ag + (size_t)r * K + koff + ch * 8);
            } else {
                int c2 = c - 1024;
                int r = c2 >> 3, ch = c2 & 7;
                cp_async16(sdst + A_ST + r * ROWB + ch * 16, Bg + (size_t)r * K + koff + ch * 8);
            }
        }
    };

    for (int s = 0; s < GNS - 1; s++) { load_stage(s, s); CP_COMMIT(); }

    float acc[4][8][4] = {};

    for (int kt = 0; kt < nk; kt++) {
        CP_WAIT(GNS - 2);
        __syncthreads();
        // Hoisted prefetch: slot (kt+2)%3 == slot (kt-1)%3, whose readers all
        // finished compute(kt-1) before passing this barrier. Gives cp.async
        // the whole compute(kt) window (~2 iterations total cover).
        if (kt + GNS - 1 < nk) load_stage((kt + GNS - 1) % GNS, kt + GNS - 1);
        CP_COMMIT();

        uint32_t sbase = sb + (kt % GNS) * STB;
#pragma unroll
        for (int ks = 0; ks < 4; ks++) {
            uint32_t kb = ks * 32;
            uint32_t aF[4][4], bF[4][4];
#pragma unroll
            for (int mt = 0; mt < 4; mt++)
                ldsm_x4(aF[mt], sbase + a_off + mt * 16 * ROWB + kb);
#pragma unroll
            for (int ng = 0; ng < 4; ng++)
                ldsm_x4(bF[ng], sbase + b_off + ng * 16 * ROWB + kb);
#pragma unroll
            for (int mt = 0; mt < 4; mt++)
#pragma unroll
                for (int ng = 0; ng < 4; ng++) {
                    mma_f16(acc[mt][ng * 2 + 0], aF[mt], &bF[ng][0]);
                    mma_f16(acc[mt][ng * 2 + 1], aF[mt], &bF[ng][2]);
                }
        }
    }

    int g = lane >> 2, tig = lane & 3;
#pragma unroll
    for (int mt = 0; mt < 4; mt++) {
#pragma unroll
        for (int nf = 0; nf < 8; nf++) {
            int row = blockIdx.y * GTM + wm * 64 + mt * 16 + g;
            int col = blockIdx.x * GTN + wn * 64 + nf * 8 + 2 * tig;
            *(__half2*)&C[(size_t)row * N + col] =
                __floats2half2_rn(acc[mt][nf][0], acc[mt][nf][1]);
            *(__half2*)&C[(size_t)(row + 8) * N + col] =
                __floats2half2_rn(acc[mt][nf][2], acc[mt][nf][3]);
        }
    }

    // ---- fused column stats (exact, from fp32 accumulators) ----
    float colS[8][2], colQ[8][2];
#pragma unroll
    for (int nf = 0; nf < 8; nf++) {
        float sA = 0.f, qA = 0.f, sB = 0.f, qB = 0.f;
#pragma unroll
        for (int mt = 0; mt < 4; mt++) {
            float v0 = acc[mt][nf][0], v1 = acc[mt][nf][1];
            float v2 = acc[mt][nf][2], v3 = acc[mt][nf][3];
            sA += v0 + v2; qA += v0 * v0 + v2 * v2;
            sB += v1 + v3; qB += v1 * v1 + v3 * v3;
        }
        colS[nf][0] = sA; colS[nf][1] = sB;
        colQ[nf][0] = qA; colQ[nf][1] = qB;
    }
#pragma unroll
    for (int m = 4; m <= 16; m <<= 1) {
#pragma unroll
        for (int nf = 0; nf < 8; nf++) {
#pragma unroll
            for (int w = 0; w < 2; w++) {
                colS[nf][w] += __shfl_xor_sync(0xFFFFFFFFu, colS[nf][w], m);
                colQ[nf][w] += __shfl_xor_sync(0xFFFFFFFFu, colQ[nf][w], m);
            }
        }
    }
    __syncthreads();
    float* sS = (float*)smem;
    float* sQ = (float*)(smem + 1024);
    if (lane < 4) {
#pragma unroll
        for (int nf = 0; nf < 8; nf++) {
#pragma unroll
            for (int w = 0; w < 2; w++) {
                int c = wn * 64 + nf * 8 + 2 * tig + w;
                sS[wm * 128 + c] = colS[nf][w];
                sQ[wm * 128 + c] = colQ[nf][w];
            }
        }
    }
    __syncthreads();
    if (t < 128) {
        float S = sS[t] + sS[128 + t];
        float Q = sQ[t] + sQ[128 + t];
        atomicAdd(&cs[blockIdx.x * GTN + t], S);
        atomicAdd(&cq[blockIdx.x * GTN + t], Q);
    }
}

// ---------------- linear logit ----------------
__global__ void linear_kernel(const float* __restrict__ sparse,
                              const float* __restrict__ dense,
                              const float* __restrict__ linW,
                              const float* __restrict__ linb) {
    int warp = (blockIdx.x * blockDim.x + threadIdx.x) >> 5;
    int lane = threadIdx.x & 31;
    if (warp >= BATCH) return;
    const float* s = sparse + (size_t)warp * 1024;
    float acc = 0.f;
    for (int k = lane; k < 1024; k += 32) acc += s[k] * linW[k];
    for (int k = lane; k < 64; k += 32) acc += dense[warp * 64 + k] * linW[1024 + k];
#pragma unroll
    for (int o = 16; o; o >>= 1) acc += __shfl_xor_sync(0xFFFFFFFFu, acc, o);
    if (lane == 0) g_lin[warp] = acc + linb[0];
}

// ---------------- apply BN + sigmoid, fp16 in place (half2-vectorized) -----
__global__ void bn_apply_kernel(__half* __restrict__ X,
                                const float* __restrict__ cs, const float* __restrict__ cq,
                                int M, int N) {
    int idx = blockIdx.x * blockDim.x + threadIdx.x;   // pair index
    if (idx * 2 >= M * N) return;
    int c = (idx * 2) % N;
    float invM = 1.0f / (float)M;
    float m0 = cs[c] * invM, m1 = cs[c + 1] * invM;
    float v0 = cq[c] * invM - m0 * m0, v1 = cq[c + 1] * invM - m1 * m1;
    __half2 x = *(__half2*)&X[idx * 2];
    float a = (__half2float(x.x) - m0) * rsqrtf(v0 + BN_EPS);
    float b = (__half2float(x.y) - m1) * rsqrtf(v1 + BN_EPS);
    *(__half2*)&X[idx * 2] = __floats2half2_rn(sigmoidf(a), sigmoidf(b));
}

// ---------------- fused BN(layer2) + sigmoid + W3 dot -> g_v ---------------
__global__ void bn_w3_kernel(const float* __restrict__ cs, const float* __restrict__ cq,
                             const float* __restrict__ W3) {
    int warp = (blockIdx.x * blockDim.x + threadIdx.x) >> 5;
    int lane = threadIdx.x & 31;
    if (warp >= BATCH) return;
    const __half* h = g_h2h + (size_t)warp * 256;
    const float invM = 1.0f / (float)BATCH;
    float acc = 0.f;
#pragma unroll
    for (int k = lane; k < 256; k += 32) {
        float mean = cs[k] * invM;
        float var = cq[k] * invM - mean * mean;
        float v = (__half2float(h[k]) - mean) * rsqrtf(var + BN_EPS);
        acc += sigmoidf(v) * W3[k];
    }
#pragma unroll
    for (int o = 16; o; o >>= 1) acc += __shfl_xor_sync(0xFFFFFFFFu, acc, o);
    if (lane == 0) g_v[warp] = acc;
}

// ---------------- fused scalar BN stats + final output ---------------------
__global__ void vstats_final_kernel(float* __restrict__ out) {
    __shared__ float ss[1024], qq[1024];
    __shared__ float stat[2];
    int t = threadIdx.x;
    float s = 0.f, q = 0.f;
#pragma unroll
    for (int i = t; i < BATCH; i += 1024) { float v = g_v[i]; s += v; q += v * v; }
    ss[t] = s; qq[t] = q;
    __syncthreads();
    for (int o = 512; o; o >>= 1) {
        if (t < o) { ss[t] += ss[t + o]; qq[t] += qq[t + o]; }
        __syncthreads();
    }
    if (t == 0) {
        float m = ss[0] / (float)BATCH;
        stat[0] = m;
        stat[1] = rsqrtf(qq[0] / (float)BATCH - m * m + BN_EPS);
    }
    __syncthreads();
    float mean = stat[0], rstd = stat[1];
#pragma unroll
    for (int i = t; i < BATCH; i += 1024) {
        float dl = sigmoidf((g_v[i] - mean) * rstd);
        out[i] = sigmoidf(g_lin[i] + dl);
    }
}

// ---------------- launch ----------------
extern "C" void kernel_launch(void* const* d_in, const int* in_sizes, int n_in,
                              void* d_out, int out_size) {
    const float* sparse = (const float*)d_in[0];
    const float* dense  = (const float*)d_in[1];
    const float* embW   = (const float*)d_in[2];
    const float* linW   = (const float*)d_in[3];
    const float* linb   = (const float*)d_in[4];
    const float* seW1   = (const float*)d_in[5];
    const float* seW2   = (const float*)d_in[6];
    const float* biW    = (const float*)d_in[7];
    const float* W0     = (const float*)d_in[8];
    const float* W1     = (const float*)d_in[10];
    const float* W2     = (const float*)d_in[12];
    const float* W3     = (const float*)d_in[14];

    void *p_dnn, *p_W0h, *p_W1h, *p_W2h, *p_biWh;
    void *p_h0h, *p_h1h, *p_h2h, *p_cs, *p_cq;
    cudaGetSymbolAddress(&p_dnn, g_dnn);
    cudaGetSymbolAddress(&p_W0h, g_W0h);
    cudaGetSymbolAddress(&p_W1h, g_W1h);
    cudaGetSymbolAddress(&p_W2h, g_W2h);
    cudaGetSymbolAddress(&p_biWh, g_biWh);
    cudaGetSymbolAddress(&p_h0h, g_h0h);
    cudaGetSymbolAddress(&p_h1h, g_h1h);
    cudaGetSymbolAddress(&p_h2h, g_h2h);
    cudaGetSymbolAddress(&p_cs, g_cs);
    cudaGetSymbolAddress(&p_cq, g_cq);
    float* cs = (float*)p_cs;
    float* cq = (float*)p_cq;

    cudaFuncSetAttribute(hgemm_kernel, cudaFuncAttributeMaxDynamicSharedMemorySize, GSMEM);

    conv_all_kernel<<<(CC_TOT + 255) / 256, 256>>>(W0, sparse, W1, W2, biW, embW, dense);
    embed_mma_kernel<<<dim3(BATCH / 128, NF), 256>>>();
    bilinear_mma_kernel<<<dim3(BATCH / 128, NPAIRS), 256>>>((const __half*)p_biWh, seW1, seW2);

    // hgemm0 at capture index 3
    hgemm_kernel<<<dim3(N0 / GTN, BATCH / GTM), 128, GSMEM>>>(
        (const __half*)p_dnn, (const __half*)p_W0h, (__half*)p_h0h, cs, cq, N0, K0);
    linear_kernel<<<BATCH / 8, 256>>>(sparse, dense, linW, linb);
    bn_apply_kernel<<<(BATCH * N0 / 2) / 256, 256>>>((__half*)p_h0h, cs, cq, BATCH, N0);

    hgemm_kernel<<<dim3(N1 / GTN, BATCH / GTM), 128, GSMEM>>>(
        (const __half*)p_h0h, (const __half*)p_W1h, (__half*)p_h1h, cs + 1024, cq + 1024, N1, N0);
    bn_apply_kernel<<<(BATCH * N1 / 2) / 256, 256>>>((__half*)p_h1h, cs + 1024, cq + 1024, BATCH, N1);

    hgemm_kernel<<<dim3(N2 / GTN, BATCH / GTM), 128, GSMEM>>>(
        (const __half*)p_h1h, (const __half*)p_W2h, (__half*)p_h2h, cs + 1536, cq + 1536, N2, N1);

    bn_w3_kernel<<<BATCH / 8, 256>>>(cs + 1536, cq + 1536, W3);
    vstats_final_kernel<<<1, 1024>>>((float*)d_out);
}

// round 17
// speedup vs baseline: 1.0169x; 1.0169x over previous
#include <cuda_runtime.h>
#include <cuda_fp16.h>
#include <cstdint>

#define BATCH 4096
#define NF 16
#define FS 64
#define EMBD 64
#define NPAIRS 120
#define K0 15424
#define N0 1024
#define N1 512
#define N2 256
#define BN_EPS 1e-5f

// ---------------- scratch ----------------
__device__ __align__(16) __half g_sparseh[BATCH * NF * FS];
__device__ __align__(16) __half g_embWh[NF * EMBD * FS];
__device__ __align__(16) __half g_embh[BATCH * NF * EMBD];
__device__ __align__(16) float  g_z[BATCH * NF];
__device__ __align__(16) __half g_dnn[(size_t)BATCH * K0];
__device__ __align__(16) __half g_W0h[(size_t)N0 * K0];
__device__ __align__(16) __half g_W1h[N1 * N0];
__device__ __align__(16) __half g_W2h[N2 * N1];
__device__ __align__(16) __half g_biWh[NPAIRS * EMBD * EMBD];
__device__ __align__(16) __half g_h0h[BATCH * N0];
__device__ __align__(16) __half g_h1h[BATCH * N1];
__device__ __align__(16) __half g_h2h[BATCH * N2];
__device__ __align__(16) float  g_cs[1792];
__device__ __align__(16) float  g_cq[1792];
__device__ float g_v[BATCH];
__device__ float g_lin[BATCH];

__device__ __forceinline__ float sigmoidf(float x) {
    return 1.0f / (1.0f + __expf(-x));
}

__device__ __forceinline__ uint32_t smem_u32(const void* p) {
    uint32_t a;
    asm("{ .reg .u64 t; cvta.to.shared.u64 t, %1; cvt.u32.u64 %0, t; }" : "=r"(a) : "l"(p));
    return a;
}

__device__ __forceinline__ void mma_f16(float c[4], const uint32_t a[4], const uint32_t b[2]) {
    asm volatile(
        "mma.sync.aligned.m16n8k16.row.col.f32.f16.f16.f32 "
        "{%0,%1,%2,%3}, {%4,%5,%6,%7}, {%8,%9}, {%0,%1,%2,%3};"
        : "+f"(c[0]), "+f"(c[1]), "+f"(c[2]), "+f"(c[3])
        : "r"(a[0]), "r"(a[1]), "r"(a[2]), "r"(a[3]), "r"(b[0]), "r"(b[1]));
}

__device__ __forceinline__ void ldsm_x4(uint32_t r[4], uint32_t addr) {
    asm volatile("ldmatrix.sync.aligned.m8n8.x4.shared.b16 {%0,%1,%2,%3}, [%4];"
        : "=r"(r[0]), "=r"(r[1]), "=r"(r[2]), "=r"(r[3]) : "r"(addr));
}
__device__ __forceinline__ void ldsm_x2(uint32_t r[2], uint32_t addr) {
    asm volatile("ldmatrix.sync.aligned.m8n8.x2.shared.b16 {%0,%1}, [%2];"
        : "=r"(r[0]), "=r"(r[1]) : "r"(addr));
}
__device__ __forceinline__ void cp_async16(uint32_t dst, const void* src) {
    asm volatile("cp.async.cg.shared.global [%0], [%1], 16;" :: "r"(dst), "l"(src));
}
#define CP_COMMIT() asm volatile("cp.async.commit_group;" ::: "memory")
#define CP_WAIT(n)  asm volatile("cp.async.wait_group %0;" :: "n"(n) : "memory")

#define ROWB 144

// ================= launch 0: fused conversions + stats zeroing =============
#define CC_W0 3948544u
#define CC_SP 4997120u
#define CC_W1 5128192u
#define CC_W2 5160960u
#define CC_BI 5283840u
#define CC_EW 5300224u
#define CC_DE 5365760u
#define CC_TOT (CC_DE + 896u)

__global__ void conv_all_kernel(const float* __restrict__ W0, const float* __restrict__ sparse,
                                const float* __restrict__ W1, const float* __restrict__ W2,
                                const float* __restrict__ biW, const float* __restrict__ embW,
                                const float* __restrict__ dense) {
    uint32_t idx = blockIdx.x * 256 + threadIdx.x;
    if (idx >= CC_TOT) return;
    const float* src;
    __half* dst;
    size_t off;
    if (idx < CC_W0)      { src = W0;     dst = g_W0h;     off = idx; }
    else if (idx < CC_SP) { src = sparse; dst = g_sparseh; off = idx - CC_W0; }
    else if (idx < CC_W1) { src = W1;     dst = g_W1h;     off = idx - CC_SP; }
    else if (idx < CC_W2) { src = W2;     dst = g_W2h;     off = idx - CC_W1; }
    else if (idx < CC_BI) { src = biW;    dst = g_biWh;    off = idx - CC_W2; }
    else if (idx < CC_EW) { src = embW;   dst = g_embWh;   off = idx - CC_BI; }
    else if (idx < CC_DE) {
        uint32_t o = (idx - CC_EW) * 4;
        int b = o >> 6, d = o & 63;
        float4 v = *(const float4*)(dense + o);
        __half2* dd = (__half2*)&g_dnn[(size_t)b * K0 + 15360 + d];
        dd[0] = __floats2half2_rn(v.x, v.y);
        dd[1] = __floats2half2_rn(v.z, v.w);
        return;
    } else {
        uint32_t k = (idx - CC_DE) * 4;
        float4 z = {0.f, 0.f, 0.f, 0.f};
        if (k < 1792) *(float4*)&g_cs[k] = z;
        else *(float4*)&g_cq[k - 1792] = z;
        return;
    }
    float4 v = *(const float4*)(src + off * 4);
    __half2* d2 = (__half2*)(dst + off * 4);
    d2[0] = __floats2half2_rn(v.x, v.y);
    d2[1] = __floats2half2_rn(v.z, v.w);
}

// ================= launch 1: embed mma + row-sum partials ==================
#define EM_X 0
#define EM_W 18432
#define EM_SMEM 27648

__global__ void __launch_bounds__(256)
embed_mma_kernel() {
    __shared__ __align__(128) char sm[EM_SMEM];
    __shared__ float zp[128][8];
    uint32_t sb = smem_u32(sm);
    int t = threadIdx.x;
    int lane = t & 31, warp = t >> 5;
    int wm = warp >> 1;
    int wn = warp & 1;
    int gg = blockIdx.y;
    int b0 = blockIdx.x * 128;

#pragma unroll
    for (int c0 = 0; c0 < 1536; c0 += 256) {
        int c = c0 + t;
        if (c < 1024) {
            int r = c >> 3, ch = c & 7;
            cp_async16(sb + EM_X + r * ROWB + ch * 16,
                       g_sparseh + (size_t)(b0 + r) * 1024 + gg * 64 + ch * 8);
        } else {
            int r = (c - 1024) >> 3, ch = c & 7;
            cp_async16(sb + EM_W + r * ROWB + ch * 16,
                       g_embWh + gg * 4096 + r * 64 + ch * 8);
        }
    }
    CP_COMMIT();
    CP_WAIT(0);
    __syncthreads();

    int q = lane >> 3, r8 = lane & 7;
    uint32_t a_off = sb + EM_X + (uint32_t)((wm * 32 + (q & 1) * 8 + r8) * ROWB + (q >> 1) * 16);
    uint32_t b_off = sb + EM_W + (uint32_t)((wn * 32 + r8) * ROWB + (q & 1) * 16);

    float acc[2][4][4] = {};
#pragma unroll
    for (int ks = 0; ks < 4; ks++) {
        uint32_t kb = ks * 32;
        uint32_t aF[2][4], bF[4][2];
#pragma unroll
        for (int mt = 0; mt < 2; mt++)
            ldsm_x4(aF[mt], a_off + mt * 16 * ROWB + kb);
#pragma unroll
        for (int nt = 0; nt < 4; nt++)
            ldsm_x2(bF[nt], b_off + nt * 8 * ROWB + kb);
#pragma unroll
        for (int mt = 0; mt < 2; mt++)
#pragma unroll
            for (int nt = 0; nt < 4; nt++)
                mma_f16(acc[mt][nt], aF[mt], bF[nt]);
    }

    int g = lane >> 2, tig = lane & 3;
#pragma unroll
    for (int mt = 0; mt < 2; mt++) {
#pragma unroll
        for (int h = 0; h < 2; h++) {
            int row = wm * 32 + mt * 16 + g + h * 8;
            float part = 0.f;
#pragma unroll
            for (int nt = 0; nt < 4; nt++) {
                int col = wn * 32 + nt * 8 + 2 * tig;
                float a0 = acc[mt][nt][h * 2 + 0], a1 = acc[mt][nt][h * 2 + 1];
                size_t base = (size_t)(b0 + row) * 1024 + gg * 64 + col;
                *(__half2*)&g_embh[base] = __floats2half2_rn(a0, a1);
                part += a0 + a1;
            }
            zp[row][wn * 4 + tig] = part;
        }
    }
    __syncthreads();
    if (t < 128) {
        float s = 0.f;
#pragma unroll
        for (int k = 0; k < 8; k++) s += zp[t][k];
        g_z[(b0 + t) * 16 + gg] = s;
    }
}

// ================= launch 2: bilinear mma + in-block senet MLP =============
#define BL_VI 0
#define BL_VJ 18432
#define BL_W  36864
#define BL_GA 46080
#define BL_SMEM 46592

__global__ void __launch_bounds__(256)
bilinear_mma_kernel(const __half* __restrict__ biWh,
                    const float* __restrict__ seW1, const float* __restrict__ seW2) {
    __shared__ __align__(128) char sm[BL_SMEM];
    uint32_t sb = smem_u32(sm);
    int t = threadIdx.x;
    int lane = t & 31, warp = t >> 5;
    int wm = warp >> 1;
    int wn = warp & 1;

    int p = blockIdx.y;
    int i = 0, rem = p, cnt = 15;
    while (rem >= cnt) { rem -= cnt; i++; cnt--; }
    int jf = i + 1 + rem;
    int b0 = blockIdx.x * 128;

#pragma unroll
    for (int c0 = 0; c0 < 2560; c0 += 256) {
        int c = c0 + t;
        if (c < 1024) {
            int r = c >> 3, ch = c & 7;
            cp_async16(sb + BL_VI + r * ROWB + ch * 16,
                       g_embh + (size_t)(b0 + r) * 1024 + i * 64 + ch * 8);
        } else if (c < 2048) {
            int r = (c - 1024) >> 3, ch = c & 7;
            cp_async16(sb + BL_VJ + r * ROWB + ch * 16,
                       g_embh + (size_t)(b0 + r) * 1024 + jf * 64 + ch * 8);
        } else {
            int r = (c - 2048) >> 3, ch = c & 7;
            cp_async16(sb + BL_W + r * ROWB + ch * 16,
                       biWh + (size_t)p * 4096 + r * 64 + ch * 8);
        }
    }
    if (t < 128) {
        int row = b0 + t;
        float zs[16];
#pragma unroll
        for (int k = 0; k < 16; k++) zs[k] = g_z[row * 16 + k] * (1.0f / 64.0f);
        float hv[4];
#pragma unroll
        for (int tt = 0; tt < 4; tt++) {
            float s = 0.f;
#pragma unroll
            for (int k = 0; k < 16; k++) s += zs[k] * seW1[tt * 16 + k];
            hv[tt] = fmaxf(s, 0.f);
        }
        float ai = 0.f, aj = 0.f;
#pragma unroll
        for (int tt = 0; tt < 4; tt++) {
            ai += hv[tt] * seW2[i * 4 + tt];
            aj += hv[tt] * seW2[jf * 4 + tt];
        }
        *(float*)(sm + BL_GA + t * 4) = fmaxf(ai, 0.f) * fmaxf(aj, 0.f);
    }
    CP_COMMIT();
    CP_WAIT(0);
    __syncthreads();

    int q = lane >> 3, r8 = lane & 7;
    uint32_t a_off = sb + BL_VI + (uint32_t)((wm * 32 + (q & 1) * 8 + r8) * ROWB + (q >> 1) * 16);
    uint32_t b_off = sb + BL_W + (uint32_t)((wn * 32 + r8) * ROWB + (q & 1) * 16);

    float acc[2][4][4] = {};
#pragma unroll
    for (int ks = 0; ks < 4; ks++) {
        uint32_t kb = ks * 32;
        uint32_t aF[2][4], bF[4][2];
#pragma unroll
        for (int mt = 0; mt < 2; mt++)
            ldsm_x4(aF[mt], a_off + mt * 16 * ROWB + kb);
#pragma unroll
        for (int nt = 0; nt < 4; nt++)
            ldsm_x2(bF[nt], b_off + nt * 8 * ROWB + kb);
#pragma unroll
        for (int mt = 0; mt < 2; mt++)
#pragma unroll
            for (int nt = 0; nt < 4; nt++)
                mma_f16(acc[mt][nt], aF[mt], bF[nt]);
    }
    __syncthreads();

    int g = lane >> 2, tig = lane & 3;
#pragma unroll
    for (int mt = 0; mt < 2; mt++) {
#pragma unroll
        for (int nt = 0; nt < 4; nt++) {
            int col = wn * 32 + nt * 8 + 2 * tig;
#pragma unroll
            for (int h = 0; h < 2; h++) {
                int row = wm * 32 + mt * 16 + g + h * 8;
                __half2 vj = *(__half2*)(sm + BL_VJ + row * ROWB + col * 2);
                float p0 = acc[mt][nt][h * 2 + 0] * __half2float(vj.x);
                float p1 = acc[mt][nt][h * 2 + 1] * __half2float(vj.y);
                *(__half2*)(sm + BL_VI + row * ROWB + col * 2) = __floats2half2_rn(p0, p1);
            }
        }
    }
    __syncthreads();

#pragma unroll
    for (int c0 = 0; c0 < 1024; c0 += 256) {
        int c = c0 + t;
        int row = c >> 3, ch = c & 7;
        uint4 v = *(uint4*)(sm + BL_VI + row * ROWB + ch * 16);
        size_t base = (size_t)(b0 + row) * K0 + p * 64 + ch * 8;
        *(uint4*)&g_dnn[base] = v;
        float s = *(float*)(sm + BL_GA + row * 4);
        __half2 s2 = __floats2half2_rn(s, s);
        __half2* hv = (__half2*)&v;
        hv[0] = __hmul2(hv[0], s2);
        hv[1] = __hmul2(hv[1], s2);
        hv[2] = __hmul2(hv[2], s2);
        hv[3] = __hmul2(hv[3], s2);
        *(uint4*)&g_dnn[base + 7680] = v;
    }
}

// ================= FP16 GEMM 128x128, 4 warps (2m x 2n, 64x64), GNS=3 ======
// 2 CTAs/SM, R14 load placement (measured optimum). fp16 C out, fused stats.
#define GTM 128
#define GTN 128
#define GBK 64
#define GNS 3
#define A_ST (GTM * ROWB)
#define B_ST (GTN * ROWB)
#define STB  (A_ST + B_ST)
#define GSMEM (GNS * STB)        // 110592

__global__ void __launch_bounds__(128, 2)
hgemm_kernel(const __half* __restrict__ A, const __half* __restrict__ Bw,
             __half* __restrict__ C, float* __restrict__ cs, float* __restrict__ cq,
             int N, int K) {
    extern __shared__ __align__(128) char smem[];
    uint32_t sb = smem_u32(smem);
    int t = threadIdx.x;
    int lane = t & 31, warp = t >> 5;
    int wm = warp & 1;
    int wn = warp >> 1;

    const __half* Ag = A + (size_t)(blockIdx.y * GTM) * K;
    const __half* Bg = Bw + (size_t)(blockIdx.x * GTN) * K;
    int nk = K / GBK;

    int q = lane >> 3, r8 = lane & 7;
    uint32_t a_off = (uint32_t)((wm * 64 + (q & 1) * 8 + r8) * ROWB + (q >> 1) * 16);
    uint32_t b_off = (uint32_t)(A_ST + (wn * 64 + (q >> 1) * 8 + r8) * ROWB + (q & 1) * 16);

    auto load_stage = [&](int slot, int kt) {
        uint32_t sdst = sb + slot * STB;
        int koff = kt * GBK;
#pragma unroll
        for (int c0 = 0; c0 < 2048; c0 += 128) {
            int c = c0 + t;
            if (c < 1024) {
                int r = c >> 3, ch = c & 7;
                cp_async16(sdst + r * ROWB + ch * 16, Ag + (size_t)r * K + koff + ch * 8);
            } else {
                int c2 = c - 1024;
                int r = c2 >> 3, ch = c2 & 7;
                cp_async16(sdst + A_ST + r * ROWB + ch * 16, Bg + (size_t)r * K + koff + ch * 8);
            }
        }
    };

    for (int s = 0; s < GNS - 1; s++) { load_stage(s, s); CP_COMMIT(); }

    float acc[4][8][4] = {};

    for (int kt = 0; kt < nk; kt++) {
        CP_WAIT(GNS - 2);
        __syncthreads();
        uint32_t sbase = sb + (kt % GNS) * STB;
#pragma unroll
        for (int ks = 0; ks < 4; ks++) {
            uint32_t kb = ks * 32;
            uint32_t aF[4][4], bF[4][4];
#pragma unroll
            for (int mt = 0; mt < 4; mt++)
                ldsm_x4(aF[mt], sbase + a_off + mt * 16 * ROWB + kb);
#pragma unroll
            for (int ng = 0; ng < 4; ng++)
                ldsm_x4(bF[ng], sbase + b_off + ng * 16 * ROWB + kb);
#pragma unroll
            for (int mt = 0; mt < 4; mt++)
#pragma unroll
                for (int ng = 0; ng < 4; ng++) {
                    mma_f16(acc[mt][ng * 2 + 0], aF[mt], &bF[ng][0]);
                    mma_f16(acc[mt][ng * 2 + 1], aF[mt], &bF[ng][2]);
                }
        }
        if (kt + GNS - 1 < nk) load_stage((kt + GNS - 1) % GNS, kt + GNS - 1);
        CP_COMMIT();
    }

    int g = lane >> 2, tig = lane & 3;
#pragma unroll
    for (int mt = 0; mt < 4; mt++) {
#pragma unroll
        for (int nf = 0; nf < 8; nf++) {
            int row = blockIdx.y * GTM + wm * 64 + mt * 16 + g;
            int col = blockIdx.x * GTN + wn * 64 + nf * 8 + 2 * tig;
            *(__half2*)&C[(size_t)row * N + col] =
                __floats2half2_rn(acc[mt][nf][0], acc[mt][nf][1]);
            *(__half2*)&C[(size_t)(row + 8) * N + col] =
                __floats2half2_rn(acc[mt][nf][2], acc[mt][nf][3]);
        }
    }

    // ---- fused column stats (exact, from fp32 accumulators) ----
    float colS[8][2], colQ[8][2];
#pragma unroll
    for (int nf = 0; nf < 8; nf++) {
        float sA = 0.f, qA = 0.f, sB = 0.f, qB = 0.f;
#pragma unroll
        for (int mt = 0; mt < 4; mt++) {
            float v0 = acc[mt][nf][0], v1 = acc[mt][nf][1];
            float v2 = acc[mt][nf][2], v3 = acc[mt][nf][3];
            sA += v0 + v2; qA += v0 * v0 + v2 * v2;
            sB += v1 + v3; qB += v1 * v1 + v3 * v3;
        }
        colS[nf][0] = sA; colS[nf][1] = sB;
        colQ[nf][0] = qA; colQ[nf][1] = qB;
    }
#pragma unroll
    for (int m = 4; m <= 16; m <<= 1) {
#pragma unroll
        for (int nf = 0; nf < 8; nf++) {
#pragma unroll
            for (int w = 0; w < 2; w++) {
                colS[nf][w] += __shfl_xor_sync(0xFFFFFFFFu, colS[nf][w], m);
                colQ[nf][w] += __shfl_xor_sync(0xFFFFFFFFu, colQ[nf][w], m);
            }
        }
    }
    __syncthreads();
    float* sS = (float*)smem;
    float* sQ = (float*)(smem + 1024);
    if (lane < 4) {
#pragma unroll
        for (int nf = 0; nf < 8; nf++) {
#pragma unroll
            for (int w = 0; w < 2; w++) {
                int c = wn * 64 + nf * 8 + 2 * tig + w;
                sS[wm * 128 + c] = colS[nf][w];
                sQ[wm * 128 + c] = colQ[nf][w];
            }
        }
    }
    __syncthreads();
    if (t < 128) {
        float S = sS[t] + sS[128 + t];
        float Q = sQ[t] + sQ[128 + t];
        atomicAdd(&cs[blockIdx.x * GTN + t], S);
        atomicAdd(&cq[blockIdx.x * GTN + t], Q);
    }
}

// ---------------- linear logit ----------------
__global__ void linear_kernel(const float* __restrict__ sparse,
                              const float* __restrict__ dense,
                              const float* __restrict__ linW,
                              const float* __restrict__ linb) {
    int warp = (blockIdx.x * blockDim.x + threadIdx.x) >> 5;
    int lane = threadIdx.x & 31;
    if (warp >= BATCH) return;
    const float* s = sparse + (size_t)warp * 1024;
    float acc = 0.f;
    for (int k = lane; k < 1024; k += 32) acc += s[k] * linW[k];
    for (int k = lane; k < 64; k += 32) acc += dense[warp * 64 + k] * linW[1024 + k];
#pragma unroll
    for (int o = 16; o; o >>= 1) acc += __shfl_xor_sync(0xFFFFFFFFu, acc, o);
    if (lane == 0) g_lin[warp] = acc + linb[0];
}

// ---------------- apply BN + sigmoid, fp16 in place (half2-vectorized) -----
__global__ void bn_apply_kernel(__half* __restrict__ X,
                                const float* __restrict__ cs, const float* __restrict__ cq,
                                int M, int N) {
    int idx = blockIdx.x * blockDim.x + threadIdx.x;   // pair index
    if (idx * 2 >= M * N) return;
    int c = (idx * 2) % N;
    float invM = 1.0f / (float)M;
    float m0 = cs[c] * invM, m1 = cs[c + 1] * invM;
    float v0 = cq[c] * invM - m0 * m0, v1 = cq[c + 1] * invM - m1 * m1;
    __half2 x = *(__half2*)&X[idx * 2];
    float a = (__half2float(x.x) - m0) * rsqrtf(v0 + BN_EPS);
    float b = (__half2float(x.y) - m1) * rsqrtf(v1 + BN_EPS);
    *(__half2*)&X[idx * 2] = __floats2half2_rn(sigmoidf(a), sigmoidf(b));
}

// ---------------- fused BN(layer2) + sigmoid + W3 dot -> g_v ---------------
__global__ void bn_w3_kernel(const float* __restrict__ cs, const float* __restrict__ cq,
                             const float* __restrict__ W3) {
    int warp = (blockIdx.x * blockDim.x + threadIdx.x) >> 5;
    int lane = threadIdx.x & 31;
    if (warp >= BATCH) return;
    const __half* h = g_h2h + (size_t)warp * 256;
    const float invM = 1.0f / (float)BATCH;
    float acc = 0.f;
#pragma unroll
    for (int k = lane; k < 256; k += 32) {
        float mean = cs[k] * invM;
        float var = cq[k] * invM - mean * mean;
        float v = (__half2float(h[k]) - mean) * rsqrtf(var + BN_EPS);
        acc += sigmoidf(v) * W3[k];
    }
#pragma unroll
    for (int o = 16; o; o >>= 1) acc += __shfl_xor_sync(0xFFFFFFFFu, acc, o);
    if (lane == 0) g_v[warp] = acc;
}

// ---------------- fused scalar BN stats + final output ---------------------
__global__ void vstats_final_kernel(float* __restrict__ out) {
    __shared__ float ss[1024], qq[1024];
    __shared__ float stat[2];
    int t = threadIdx.x;
    float s = 0.f, q = 0.f;
#pragma unroll
    for (int i = t; i < BATCH; i += 1024) { float v = g_v[i]; s += v; q += v * v; }
    ss[t] = s; qq[t] = q;
    __syncthreads();
    for (int o = 512; o; o >>= 1) {
        if (t < o) { ss[t] += ss[t + o]; qq[t] += qq[t + o]; }
        __syncthreads();
    }
    if (t == 0) {
        float m = ss[0] / (float)BATCH;
        stat[0] = m;
        stat[1] = rsqrtf(qq[0] / (float)BATCH - m * m + BN_EPS);
    }
    __syncthreads();
    float mean = stat[0], rstd = stat[1];
#pragma unroll
    for (int i = t; i < BATCH; i += 1024) {
        float dl = sigmoidf((g_v[i] - mean) * rstd);
        out[i] = sigmoidf(g_lin[i] + dl);
    }
}

// ---------------- launch ----------------
extern "C" void kernel_launch(void* const* d_in, const int* in_sizes, int n_in,
                              void* d_out, int out_size) {
    const float* sparse = (const float*)d_in[0];
    const float* dense  = (const float*)d_in[1];
    const float* embW   = (const float*)d_in[2];
    const float* linW   = (const float*)d_in[3];
    const float* linb   = (const float*)d_in[4];
    const float* seW1   = (const float*)d_in[5];
    const float* seW2   = (const float*)d_in[6];
    const float* biW    = (const float*)d_in[7];
    const float* W0     = (const float*)d_in[8];
    const float* W1     = (const float*)d_in[10];
    const float* W2     = (const float*)d_in[12];
    const float* W3     = (const float*)d_in[14];

    void *p_dnn, *p_W0h, *p_W1h, *p_W2h, *p_biWh;
    void *p_h0h, *p_h1h, *p_h2h, *p_cs, *p_cq;
    cudaGetSymbolAddress(&p_dnn, g_dnn);
    cudaGetSymbolAddress(&p_W0h, g_W0h);
    cudaGetSymbolAddress(&p_W1h, g_W1h);
    cudaGetSymbolAddress(&p_W2h, g_W2h);
    cudaGetSymbolAddress(&p_biWh, g_biWh);
    cudaGetSymbolAddress(&p_h0h, g_h0h);
    cudaGetSymbolAddress(&p_h1h, g_h1h);
    cudaGetSymbolAddress(&p_h2h, g_h2h);
    cudaGetSymbolAddress(&p_cs, g_cs);
    cudaGetSymbolAddress(&p_cq, g_cq);
    float* cs = (float*)p_cs;
    float* cq = (float*)p_cq;

    cudaFuncSetAttribute(hgemm_kernel, cudaFuncAttributeMaxDynamicSharedMemorySize, GSMEM);

    conv_all_kernel<<<(CC_TOT + 255) / 256, 256>>>(W0, sparse, W1, W2, biW, embW, dense);
    embed_mma_kernel<<<dim3(BATCH / 128, NF), 256>>>();
    bilinear_mma_kernel<<<dim3(BATCH / 128, NPAIRS), 256>>>((const __half*)p_biWh, seW1, seW2);

    hgemm_kernel<<<dim3(N0 / GTN, BATCH / GTM), 128, GSMEM>>>(
        (const __half*)p_dnn, (const __half*)p_W0h, (__half*)p_h0h, cs, cq, N0, K0);
    linear_kernel<<<BATCH / 8, 256>>>(sparse, dense, linW, linb);
    bn_apply_kernel<<<(BATCH * N0 / 2) / 256, 256>>>((__half*)p_h0h, cs, cq, BATCH, N0);

    hgemm_kernel<<<dim3(N1 / GTN, BATCH / GTM), 128, GSMEM>>>(
        (const __half*)p_h0h, (const __half*)p_W1h, (__half*)p_h1h, cs + 1024, cq + 1024, N1, N0);
    bn_apply_kernel<<<(BATCH * N1 / 2) / 256, 256>>>((__half*)p_h1h, cs + 1024, cq + 1024, BATCH, N1);

    hgemm_kernel<<<dim3(N2 / GTN, BATCH / GTM), 128, GSMEM>>>(
        (const __half*)p_h1h, (const __half*)p_W2h, (__half*)p_h2h, cs + 1536, cq + 1536, N2, N1);

    bn_w3_kernel<<<BATCH / 8, 256>>>(cs + 1536, cq + 1536, W3);
    vstats_final_kernel<<<1, 1024>>>((float*)d_out);
}